// round 4
// baseline (speedup 1.0000x reference)
#include <cuda_runtime.h>
#include <cstdint>

// FieldAwareInteractionLayer:
//   X:     int32  [4096, 39]
//   table: f32    [100000, 39, 16]
//   out:   f32    [4096, 741, 16]
//   out[b, p, :] = table[X[b,iu[p]], ju[p], :] * table[X[b,ju[p]], iu[p], :]
// with (iu, ju) = upper-triangle pairs (k=1) in row-major order.

#define FIELDS   39
#define EMB      16
#define PAIRS    741            // 39*38/2
#define ROW_F4   (FIELDS * EMB / 4)   // 156 float4 per table row
#define OUT_F4   (PAIRS * 4)          // 2964 float4 per batch row
#define THREADS  256

__global__ void __launch_bounds__(THREADS)
ffm_interact_kernel(const int* __restrict__ X,
                    const float4* __restrict__ table,
                    float4* __restrict__ out)
{
    __shared__ int            s_x[FIELDS];
    __shared__ unsigned short s_pair[PAIRS];

    const int b   = blockIdx.x;
    const int tid = threadIdx.x;

    if (tid < FIELDS)
        s_x[tid] = X[b * FIELDS + tid];

    // Build pair table: row i has (38 - i) pairs, j = i+1 .. 38.
    for (int p = tid; p < PAIRS; p += THREADS) {
        int i = 0, rem = p;
        while (rem >= (FIELDS - 1 - i)) { rem -= (FIELDS - 1 - i); ++i; }
        int j = i + 1 + rem;
        s_pair[p] = (unsigned short)((i << 8) | j);
    }
    __syncthreads();

    float4* o = out + (size_t)b * OUT_F4;

    #pragma unroll 4
    for (int idx = tid; idx < OUT_F4; idx += THREADS) {
        const int p = idx >> 2;
        const int q = idx & 3;
        const int pr = s_pair[p];
        const int i = pr >> 8;
        const int j = pr & 0xFF;

        // left  = table[X[b,i]][j][4q..4q+3]
        // right = table[X[b,j]][i][4q..4q+3]
        const float4 L = __ldg(&table[s_x[i] * ROW_F4 + j * (EMB / 4) + q]);
        const float4 R = __ldg(&table[s_x[j] * ROW_F4 + i * (EMB / 4) + q]);

        float4 r;
        r.x = L.x * R.x;
        r.y = L.y * R.y;
        r.z = L.z * R.z;
        r.w = L.w * R.w;
        o[idx] = r;
    }
}

extern "C" void kernel_launch(void* const* d_in, const int* in_sizes, int n_in,
                              void* d_out, int out_size)
{
    const int*    X     = (const int*)d_in[0];        // [4096, 39] int32
    const float4* table = (const float4*)d_in[1];     // [100000, 39, 16] f32
    float4*       out   = (float4*)d_out;             // [4096, 741, 16] f32

    const int batch = in_sizes[0] / FIELDS;           // 4096

    ffm_interact_kernel<<<batch, THREADS>>>(X, table, out);
}

// round 10
// speedup vs baseline: 1.0271x; 1.0271x over previous
#include <cuda_runtime.h>
#include <cstdint>

// FieldAwareInteractionLayer:
//   X:     int32  [4096, 39]
//   table: f32    [100000, 39, 16]
//   out:   f32    [4096, 741, 16]
//   out[b, p, :] = table[X[b,iu[p]], ju[p], :] * table[X[b,ju[p]], iu[p], :]
// with (iu, ju) = upper-triangle pairs (k=1) in row-major order.
//
// HBM-bound (R4 ncu: DRAM=75.8%, 489 MB moved). Writes (194 MB) compulsory;
// reads have ~100 MB recoverable L2 reuse. L2 bias: evict-first streaming
// stores (output never re-read) + evict-last table loads. ptxas on sm_103
// only allows .L2::evict_last on 256-bit loads, so gathers are LDG.256
// (v8.b32) — all accessed segments are 32B-aligned (row stride 2496B = 39*64B).

#define FIELDS   39
#define EMB      16
#define PAIRS    741                  // 39*38/2
#define ROW_F4   (FIELDS * EMB / 4)   // 156 float4 per table row
#define OUT_C32  (PAIRS * 2)          // 1482 32-byte chunks per batch row
#define THREADS  256

// 256-bit gather with evict_last L2 policy. p must be 32B-aligned.
__device__ __forceinline__ void ldg_el_256(const float4* p, float4& a, float4& b)
{
    unsigned r0, r1, r2, r3, r4, r5, r6, r7;
    asm volatile(
        "ld.global.nc.L2::evict_last.v8.b32 {%0,%1,%2,%3,%4,%5,%6,%7}, [%8];"
        : "=r"(r0), "=r"(r1), "=r"(r2), "=r"(r3),
          "=r"(r4), "=r"(r5), "=r"(r6), "=r"(r7)
        : "l"(p));
    a.x = __uint_as_float(r0); a.y = __uint_as_float(r1);
    a.z = __uint_as_float(r2); a.w = __uint_as_float(r3);
    b.x = __uint_as_float(r4); b.y = __uint_as_float(r5);
    b.z = __uint_as_float(r6); b.w = __uint_as_float(r7);
}

__device__ __forceinline__ void stg_streaming(float4* p, float4 v)
{
    asm volatile("st.global.cs.v4.f32 [%0], {%1,%2,%3,%4};"
                 :: "l"(p), "f"(v.x), "f"(v.y), "f"(v.z), "f"(v.w)
                 : "memory");
}

__global__ void __launch_bounds__(THREADS)
ffm_interact_kernel(const int* __restrict__ X,
                    const float4* __restrict__ table,
                    float4* __restrict__ out)
{
    __shared__ int            s_x[FIELDS];
    __shared__ unsigned short s_pair[PAIRS];

    const int b   = blockIdx.x;
    const int tid = threadIdx.x;

    if (tid < FIELDS)
        s_x[tid] = X[b * FIELDS + tid];

    // Build pair table: row i has (38 - i) pairs, j = i+1 .. 38.
    for (int p = tid; p < PAIRS; p += THREADS) {
        int i = 0, rem = p;
        while (rem >= (FIELDS - 1 - i)) { rem -= (FIELDS - 1 - i); ++i; }
        int j = i + 1 + rem;
        s_pair[p] = (unsigned short)((i << 8) | j);
    }
    __syncthreads();

    float4* o = out + (size_t)b * (PAIRS * 4);

    #pragma unroll 3
    for (int idx = tid; idx < OUT_C32; idx += THREADS) {
        const int p = idx >> 1;
        const int h = idx & 1;          // which 32B half of the 64B segment
        const int pr = s_pair[p];
        const int i = pr >> 8;
        const int j = pr & 0xFF;

        // left  = table[X[b,i]][j][8h .. 8h+7]
        // right = table[X[b,j]][i][8h .. 8h+7]
        float4 L0, L1, R0, R1;
        ldg_el_256(&table[s_x[i] * ROW_F4 + j * (EMB / 4) + h * 2], L0, L1);
        ldg_el_256(&table[s_x[j] * ROW_F4 + i * (EMB / 4) + h * 2], R0, R1);

        float4 r0, r1;
        r0.x = L0.x * R0.x; r0.y = L0.y * R0.y;
        r0.z = L0.z * R0.z; r0.w = L0.w * R0.w;
        r1.x = L1.x * R1.x; r1.y = L1.y * R1.y;
        r1.z = L1.z * R1.z; r1.w = L1.w * R1.w;

        stg_streaming(&o[idx * 2],     r0);
        stg_streaming(&o[idx * 2 + 1], r1);
    }
}

extern "C" void kernel_launch(void* const* d_in, const int* in_sizes, int n_in,
                              void* d_out, int out_size)
{
    const int*    X     = (const int*)d_in[0];        // [4096, 39] int32
    const float4* table = (const float4*)d_in[1];     // [100000, 39, 16] f32
    float4*       out   = (float4*)d_out;             // [4096, 741, 16] f32

    const int batch = in_sizes[0] / FIELDS;           // 4096

    ffm_interact_kernel<<<batch, THREADS>>>(X, table, out);
}